// round 3
// baseline (speedup 1.0000x reference)
#include <cuda_runtime.h>
#include <math.h>

#define HID   1024
#define FF    4096
#define NE    8
#define NT    2048          // B*S tokens
#define NSLOT (NT*2)        // top-2 slots
#define BM    64
#define BN    64
#define BK    16
#define MAX_TILES 80        // worst case: 4096/64 + (NE-1) = 71

// ---------------- scratch (static device globals; no allocation) ------------
__device__ int   g_top_i[NT*2];
__device__ float g_top_w[NT*2];
__device__ int   g_slot_token[NSLOT];     // slot -> token, grouped by expert
__device__ int   g_token_slot[NT*2];      // (token,k) -> slot
__device__ int   g_tile_e[MAX_TILES];
__device__ int   g_tile_row0[MAX_TILES];
__device__ int   g_tile_nrows[MAX_TILES];
__device__ int   g_num_tiles;
__device__ float g_hidden[(size_t)NSLOT*FF];   // 64 MB
__device__ float g_dout[(size_t)NSLOT*HID];    // 16 MB

// ---------------- 1) router: logits -> softmax -> top2 -> re-softmax -------
__global__ void router_kernel(const float* __restrict__ x,
                              const float* __restrict__ gw)
{
    int wid  = (blockIdx.x * blockDim.x + threadIdx.x) >> 5;
    int lane = threadIdx.x & 31;
    if (wid >= NT) return;
    const float* xr = x + (size_t)wid * HID;

    float acc[NE];
    #pragma unroll
    for (int e = 0; e < NE; e++) acc[e] = 0.f;

    for (int h = lane; h < HID; h += 32) {
        float  xv = xr[h];
        float4 a  = *(const float4*)(gw + h*NE);
        float4 b  = *(const float4*)(gw + h*NE + 4);
        acc[0] += xv*a.x; acc[1] += xv*a.y; acc[2] += xv*a.z; acc[3] += xv*a.w;
        acc[4] += xv*b.x; acc[5] += xv*b.y; acc[6] += xv*b.z; acc[7] += xv*b.w;
    }
    #pragma unroll
    for (int e = 0; e < NE; e++) {
        #pragma unroll
        for (int o = 16; o > 0; o >>= 1)
            acc[e] += __shfl_xor_sync(0xffffffffu, acc[e], o);
    }
    if (lane == 0) {
        float m = acc[0];
        #pragma unroll
        for (int e = 1; e < NE; e++) m = fmaxf(m, acc[e]);
        float p[NE], s = 0.f;
        #pragma unroll
        for (int e = 0; e < NE; e++) { p[e] = expf(acc[e] - m); s += p[e]; }
        float inv = 1.f / s;
        #pragma unroll
        for (int e = 0; e < NE; e++) p[e] *= inv;
        int i0 = 0;
        #pragma unroll
        for (int e = 1; e < NE; e++) if (p[e] > p[i0]) i0 = e;
        int i1 = (i0 == 0) ? 1 : 0;
        #pragma unroll
        for (int e = 0; e < NE; e++) if (e != i0 && p[e] > p[i1]) i1 = e;
        // re-softmax over the two top PROBS (matches reference exactly)
        float w0 = 1.f / (1.f + expf(p[i1] - p[i0]));
        g_top_i[wid*2]   = i0;  g_top_i[wid*2+1] = i1;
        g_top_w[wid*2]   = w0;  g_top_w[wid*2+1] = 1.f - w0;
    }
}

// ---------------- 2) deterministic routing build (1 block, warp/expert) ----
__global__ void route_build_kernel()
{
    __shared__ int counts[NE];
    __shared__ int offsets[NE+1];
    const int tid  = threadIdx.x;
    const int warp = tid >> 5;      // 8 warps == 8 experts
    const int lane = tid & 31;

    // pass 1: count slots per expert
    int c = 0;
    for (int p = lane; p < NSLOT; p += 32)
        if (g_top_i[p] == warp) c++;
    #pragma unroll
    for (int o = 16; o > 0; o >>= 1) c += __shfl_down_sync(0xffffffffu, c, o);
    if (lane == 0) counts[warp] = c;
    __syncthreads();

    if (tid == 0) {
        int s = 0;
        for (int e = 0; e < NE; e++) { offsets[e] = s; s += counts[e]; }
        offsets[NE] = s;
    }
    __syncthreads();

    // pass 2: stable placement (ordered ballot scan) -> fully deterministic
    int base = offsets[warp];
    for (int p0 = 0; p0 < NSLOT; p0 += 32) {
        int p = p0 + lane;
        bool mflag = (g_top_i[p] == warp);
        unsigned mask = __ballot_sync(0xffffffffu, mflag);
        if (mflag) {
            int slot = base + __popc(mask & ((1u << lane) - 1u));
            g_slot_token[slot] = p >> 1;   // token index
            g_token_slot[p]    = slot;
        }
        base += __popc(mask);
    }
    __syncthreads();

    // tile table for grouped GEMMs
    if (tid == 0) {
        int nt = 0;
        for (int e = 0; e < NE; e++) {
            int cnt = counts[e];
            for (int r = 0; r < cnt; r += BM) {
                g_tile_e[nt]     = e;
                g_tile_row0[nt]  = offsets[e] + r;
                g_tile_nrows[nt] = min(BM, cnt - r);
                nt++;
            }
        }
        g_num_tiles = nt;
    }
}

// ---------------- 3) grouped GEMM1: [rows,H]x[H,F] dual (gate,up) + SwiGLU -
__global__ __launch_bounds__(256)
void gemm1_kernel(const float* __restrict__ x,
                  const float* __restrict__ wgate,
                  const float* __restrict__ wup)
{
    const int tile = blockIdx.x;
    if (tile >= g_num_tiles) return;
    const int e     = g_tile_e[tile];
    const int row0  = g_tile_row0[tile];
    const int nrows = g_tile_nrows[tile];
    const int n0    = blockIdx.y * BN;

    __shared__ float As[BK][BM+4];
    __shared__ float Bg[BK][BN];
    __shared__ float Bu[BK][BN];
    __shared__ int   stok[BM];

    const int tid = threadIdx.x;
    if (tid < BM) stok[tid] = (tid < nrows) ? g_slot_token[row0 + tid] : -1;
    __syncthreads();

    const int tx = tid & 15, ty = tid >> 4;
    const int am = tid >> 2, ak = (tid & 3) << 2;
    const int bk = tid >> 4, bn = (tid & 15) << 2;
    const int atok = stok[am];

    const float* wg_e = wgate + (size_t)e * HID * FF;
    const float* wu_e = wup   + (size_t)e * HID * FF;

    float cg[4][4]; float cu[4][4];
    #pragma unroll
    for (int i = 0; i < 4; i++)
        #pragma unroll
        for (int j = 0; j < 4; j++) { cg[i][j] = 0.f; cu[i][j] = 0.f; }

    for (int k0 = 0; k0 < HID; k0 += BK) {
        float4 av = make_float4(0.f, 0.f, 0.f, 0.f);
        if (atok >= 0) av = *(const float4*)(x + (size_t)atok*HID + k0 + ak);
        As[ak+0][am] = av.x; As[ak+1][am] = av.y;
        As[ak+2][am] = av.z; As[ak+3][am] = av.w;
        *(float4*)&Bg[bk][bn] = *(const float4*)(wg_e + (size_t)(k0+bk)*FF + n0 + bn);
        *(float4*)&Bu[bk][bn] = *(const float4*)(wu_e + (size_t)(k0+bk)*FF + n0 + bn);
        __syncthreads();

        #pragma unroll
        for (int kk = 0; kk < BK; kk++) {
            float a[4];
            #pragma unroll
            for (int i = 0; i < 4; i++) a[i] = As[kk][(ty<<2)+i];
            float4 bgv = *(float4*)&Bg[kk][tx<<2];
            float4 buv = *(float4*)&Bu[kk][tx<<2];
            float bga[4] = {bgv.x, bgv.y, bgv.z, bgv.w};
            float bua[4] = {buv.x, buv.y, buv.z, buv.w};
            #pragma unroll
            for (int i = 0; i < 4; i++)
                #pragma unroll
                for (int j = 0; j < 4; j++) {
                    cg[i][j] += a[i] * bga[j];
                    cu[i][j] += a[i] * bua[j];
                }
        }
        __syncthreads();
    }

    #pragma unroll
    for (int i = 0; i < 4; i++) {
        int m = (ty<<2) + i;
        if (m < nrows) {
            float* dst = g_hidden + (size_t)(row0+m)*FF + n0 + (tx<<2);
            #pragma unroll
            for (int j = 0; j < 4; j++) {
                float g = cg[i][j];
                dst[j] = (g / (1.f + __expf(-g))) * cu[i][j];   // silu(g)*u
            }
        }
    }
}

// ---------------- 4) grouped GEMM2: [rows,F]x[F,H] down-proj ---------------
__global__ __launch_bounds__(256)
void gemm2_kernel(const float* __restrict__ wdown)
{
    const int tile = blockIdx.x;
    if (tile >= g_num_tiles) return;
    const int e     = g_tile_e[tile];
    const int row0  = g_tile_row0[tile];
    const int nrows = g_tile_nrows[tile];
    const int n0    = blockIdx.y * BN;

    __shared__ float As[BK][BM+4];
    __shared__ float Bs[BK][BN];

    const int tid = threadIdx.x;
    const int tx = tid & 15, ty = tid >> 4;
    const int am = tid >> 2, ak = (tid & 3) << 2;
    const int bk = tid >> 4, bn = (tid & 15) << 2;

    const float* wd_e = wdown + (size_t)e * FF * HID;

    float c[4][4];
    #pragma unroll
    for (int i = 0; i < 4; i++)
        #pragma unroll
        for (int j = 0; j < 4; j++) c[i][j] = 0.f;

    for (int k0 = 0; k0 < FF; k0 += BK) {
        float4 av = make_float4(0.f, 0.f, 0.f, 0.f);
        if (am < nrows) av = *(const float4*)(g_hidden + (size_t)(row0+am)*FF + k0 + ak);
        As[ak+0][am] = av.x; As[ak+1][am] = av.y;
        As[ak+2][am] = av.z; As[ak+3][am] = av.w;
        *(float4*)&Bs[bk][bn] = *(const float4*)(wd_e + (size_t)(k0+bk)*HID + n0 + bn);
        __syncthreads();

        #pragma unroll
        for (int kk = 0; kk < BK; kk++) {
            float a[4];
            #pragma unroll
            for (int i = 0; i < 4; i++) a[i] = As[kk][(ty<<2)+i];
            float4 bv = *(float4*)&Bs[kk][tx<<2];
            float ba[4] = {bv.x, bv.y, bv.z, bv.w};
            #pragma unroll
            for (int i = 0; i < 4; i++)
                #pragma unroll
                for (int j = 0; j < 4; j++) c[i][j] += a[i] * ba[j];
        }
        __syncthreads();
    }

    #pragma unroll
    for (int i = 0; i < 4; i++) {
        int m = (ty<<2) + i;
        if (m < nrows) {
            float* dst = g_dout + (size_t)(row0+m)*HID + n0 + (tx<<2);
            #pragma unroll
            for (int j = 0; j < 4; j++) dst[j] = c[i][j];
        }
    }
}

// ---------------- 5) combine: out[t] = w0*D[s0] + w1*D[s1] -----------------
__global__ void combine_kernel(float* __restrict__ out)
{
    const int t  = blockIdx.x;
    const int s0 = g_token_slot[t*2];
    const int s1 = g_token_slot[t*2+1];
    const float w0 = g_top_w[t*2];
    const float w1 = g_top_w[t*2+1];
    const int h = threadIdx.x << 2;  // 256 threads * 4 = 1024 = HID
    float4 d0 = *(const float4*)(g_dout + (size_t)s0*HID + h);
    float4 d1 = *(const float4*)(g_dout + (size_t)s1*HID + h);
    float4 o;
    o.x = w0*d0.x + w1*d1.x;
    o.y = w0*d0.y + w1*d1.y;
    o.z = w0*d0.z + w1*d1.z;
    o.w = w0*d0.w + w1*d1.w;
    *(float4*)(out + (size_t)t*HID + h) = o;
}

// ---------------------------------------------------------------------------
extern "C" void kernel_launch(void* const* d_in, const int* in_sizes, int n_in,
                              void* d_out, int out_size)
{
    const float* x      = (const float*)d_in[0];
    const float* gate_w = (const float*)d_in[1];
    const float* w_gate = (const float*)d_in[2];
    const float* w_up   = (const float*)d_in[3];
    const float* w_down = (const float*)d_in[4];
    float* out = (float*)d_out;

    router_kernel<<<NT*32/256, 256>>>(x, gate_w);
    route_build_kernel<<<1, 256>>>();
    dim3 g1(MAX_TILES, FF/BN);   // 80 x 64, inactive tiles early-exit
    gemm1_kernel<<<g1, 256>>>(x, w_gate, w_up);
    dim3 g2(MAX_TILES, HID/BN);  // 80 x 16
    gemm2_kernel<<<g2, 256>>>(w_down);
    combine_kernel<<<NT, 256>>>(out);
}

// round 7
// speedup vs baseline: 2.3609x; 2.3609x over previous
#include <cuda_runtime.h>
#include <cuda_bf16.h>
#include <math.h>
#include <stdint.h>

#define HID   1024
#define FF    4096
#define NE    8
#define NT    2048
#define NSLOT (NT*2)
#define BM    128
#define BN    64
#define KC    32
#define MAX_TILES 40

// ---------------- scratch (static device globals; no allocation) ------------
__device__ __align__(256) int   g_top_i[NT*2];
__device__ __align__(256) float g_top_w[NT*2];
__device__ __align__(256) int   g_slot_token[NSLOT];
__device__ __align__(256) int   g_token_slot[NT*2];
__device__ __align__(256) int   g_tile_e[MAX_TILES];
__device__ __align__(256) int   g_tile_row0[MAX_TILES];
__device__ __align__(256) int   g_tile_nrows[MAX_TILES];
__device__ int   g_num_tiles;

// bf16 hi/lo planes, native layouts (no transpose)
__device__ __align__(256) __nv_bfloat16 g_xh[NT*HID];
__device__ __align__(256) __nv_bfloat16 g_xl[NT*HID];
__device__ __align__(256) __nv_bfloat16 g_wgh[(size_t)NE*HID*FF];
__device__ __align__(256) __nv_bfloat16 g_wgl[(size_t)NE*HID*FF];
__device__ __align__(256) __nv_bfloat16 g_wuh[(size_t)NE*HID*FF];
__device__ __align__(256) __nv_bfloat16 g_wul[(size_t)NE*HID*FF];
__device__ __align__(256) __nv_bfloat16 g_wdh[(size_t)NE*FF*HID];
__device__ __align__(256) __nv_bfloat16 g_wdl[(size_t)NE*FF*HID];
__device__ __align__(256) __nv_bfloat16 g_hh[(size_t)NSLOT*FF];
__device__ __align__(256) __nv_bfloat16 g_hl[(size_t)NSLOT*FF];
__device__ __align__(256) float g_dout[(size_t)NSLOT*HID];

// ---------------- helpers ---------------------------------------------------
__device__ __forceinline__ uint32_t smem_u32(const void* p) {
    uint32_t a;
    asm("{ .reg .u64 t; cvta.to.shared.u64 t, %1; cvt.u32.u64 %0, t; }" : "=r"(a) : "l"(p));
    return a;
}
__device__ __forceinline__ void cp16(uint32_t dst, const void* src) {
    asm volatile("cp.async.cg.shared.global [%0], [%1], 16;"
        :: "r"(dst), "l"(__cvta_generic_to_global(src)) : "memory");
}
#define CP_COMMIT() asm volatile("cp.async.commit_group;" ::: "memory")
#define CP_WAIT0()  asm volatile("cp.async.wait_group 0;" ::: "memory")

__device__ __forceinline__ void ldsm4(uint32_t* r, uint32_t addr) {
    asm volatile("ldmatrix.sync.aligned.m8n8.x4.shared.b16 {%0,%1,%2,%3}, [%4];"
        : "=r"(r[0]), "=r"(r[1]), "=r"(r[2]), "=r"(r[3]) : "r"(addr));
}
__device__ __forceinline__ void ldsm4t(uint32_t* r, uint32_t addr) {
    asm volatile("ldmatrix.sync.aligned.m8n8.x4.trans.shared.b16 {%0,%1,%2,%3}, [%4];"
        : "=r"(r[0]), "=r"(r[1]), "=r"(r[2]), "=r"(r[3]) : "r"(addr));
}
__device__ __forceinline__ void mma16816(float* d, const uint32_t* a, const uint32_t* b) {
    asm volatile("mma.sync.aligned.m16n8k16.row.col.f32.bf16.bf16.f32 "
        "{%0,%1,%2,%3}, {%4,%5,%6,%7}, {%8,%9}, {%0,%1,%2,%3};"
        : "+f"(d[0]), "+f"(d[1]), "+f"(d[2]), "+f"(d[3])
        : "r"(a[0]), "r"(a[1]), "r"(a[2]), "r"(a[3]), "r"(b[0]), "r"(b[1]));
}
__device__ __forceinline__ uint32_t pack_bf16(float a, float b) {
    unsigned short lo = __bfloat16_as_ushort(__float2bfloat16_rn(a));
    unsigned short hi = __bfloat16_as_ushort(__float2bfloat16_rn(b));
    return (uint32_t)lo | ((uint32_t)hi << 16);
}

// SMEM tile strides (bytes): conflict-free for ldmatrix
#define A_STRIDE 80     // 64B data (32 bf16) + 16B pad
#define B_STRIDE 144    // 128B data (64 bf16) + 16B pad

// ---------------- split convert: dst selected ON DEVICE (the R5/R6 bug fix) -
__global__ void split_kernel(const float* __restrict__ src, int which)
{
    // Resolve destination planes via device-side symbol references.
    __nv_bfloat16* dh; __nv_bfloat16* dl;
    switch (which) {
        case 0:  dh = g_xh;  dl = g_xl;  break;
        case 1:  dh = g_wgh; dl = g_wgl; break;
        case 2:  dh = g_wuh; dl = g_wul; break;
        default: dh = g_wdh; dl = g_wdl; break;
    }
    size_t i = (size_t)blockIdx.x * blockDim.x + threadIdx.x;   // float4 index
    float4 v = *(const float4*)(src + i * 4);
    float h0 = __bfloat162float(__float2bfloat16_rn(v.x));
    float h1 = __bfloat162float(__float2bfloat16_rn(v.y));
    float h2 = __bfloat162float(__float2bfloat16_rn(v.z));
    float h3 = __bfloat162float(__float2bfloat16_rn(v.w));
    *(uint2*)(dh + i*4) = make_uint2(pack_bf16(v.x, v.y), pack_bf16(v.z, v.w));
    *(uint2*)(dl + i*4) = make_uint2(pack_bf16(v.x - h0, v.y - h1), pack_bf16(v.z - h2, v.w - h3));
}

// ---------------- router ----------------------------------------------------
__global__ void router_kernel(const float* __restrict__ x, const float* __restrict__ gw)
{
    int wid  = (blockIdx.x * blockDim.x + threadIdx.x) >> 5;
    int lane = threadIdx.x & 31;
    if (wid >= NT) return;
    const float* xr = x + (size_t)wid * HID;
    float acc[NE];
    #pragma unroll
    for (int e = 0; e < NE; e++) acc[e] = 0.f;
    for (int h = lane; h < HID; h += 32) {
        float  xv = xr[h];
        float4 a  = *(const float4*)(gw + h*NE);
        float4 b  = *(const float4*)(gw + h*NE + 4);
        acc[0] += xv*a.x; acc[1] += xv*a.y; acc[2] += xv*a.z; acc[3] += xv*a.w;
        acc[4] += xv*b.x; acc[5] += xv*b.y; acc[6] += xv*b.z; acc[7] += xv*b.w;
    }
    #pragma unroll
    for (int e = 0; e < NE; e++)
        #pragma unroll
        for (int o = 16; o > 0; o >>= 1)
            acc[e] += __shfl_xor_sync(0xffffffffu, acc[e], o);
    if (lane == 0) {
        float m = acc[0];
        #pragma unroll
        for (int e = 1; e < NE; e++) m = fmaxf(m, acc[e]);
        float p[NE], s = 0.f;
        #pragma unroll
        for (int e = 0; e < NE; e++) { p[e] = expf(acc[e] - m); s += p[e]; }
        float inv = 1.f / s;
        #pragma unroll
        for (int e = 0; e < NE; e++) p[e] *= inv;
        int i0 = 0;
        #pragma unroll
        for (int e = 1; e < NE; e++) if (p[e] > p[i0]) i0 = e;
        int i1 = (i0 == 0) ? 1 : 0;
        #pragma unroll
        for (int e = 0; e < NE; e++) if (e != i0 && p[e] > p[i1]) i1 = e;
        float w0 = 1.f / (1.f + expf(p[i1] - p[i0]));
        g_top_i[wid*2]   = i0;  g_top_i[wid*2+1] = i1;
        g_top_w[wid*2]   = w0;  g_top_w[wid*2+1] = 1.f - w0;
    }
}

// ---------------- routing build (deterministic) ------------------------------
__global__ void route_build_kernel()
{
    __shared__ int counts[NE];
    __shared__ int offsets[NE+1];
    const int tid  = threadIdx.x;
    const int warp = tid >> 5;
    const int lane = tid & 31;
    int c = 0;
    for (int p = lane; p < NSLOT; p += 32)
        if (g_top_i[p] == warp) c++;
    #pragma unroll
    for (int o = 16; o > 0; o >>= 1) c += __shfl_down_sync(0xffffffffu, c, o);
    if (lane == 0) counts[warp] = c;
    __syncthreads();
    if (tid == 0) {
        int s = 0;
        for (int e = 0; e < NE; e++) { offsets[e] = s; s += counts[e]; }
        offsets[NE] = s;
    }
    __syncthreads();
    int base = offsets[warp];
    for (int p0 = 0; p0 < NSLOT; p0 += 32) {
        int p = p0 + lane;
        bool f = (g_top_i[p] == warp);
        unsigned msk = __ballot_sync(0xffffffffu, f);
        if (f) {
            int slot = base + __popc(msk & ((1u << lane) - 1u));
            g_slot_token[slot] = p >> 1;
            g_token_slot[p]    = slot;
        }
        base += __popc(msk);
    }
    __syncthreads();
    if (tid == 0) {
        int nt = 0;
        for (int e = 0; e < NE; e++) {
            int cnt = counts[e];
            for (int r = 0; r < cnt; r += BM) {
                g_tile_e[nt] = e;
                g_tile_row0[nt] = offsets[e] + r;
                g_tile_nrows[nt] = min(BM, cnt - r);
                nt++;
            }
        }
        g_num_tiles = nt;
    }
}

// ---------------- GEMM1: mma.sync bf16x3, gate+up, fused SwiGLU -------------
__global__ void __launch_bounds__(256) gemm1_kernel()
{
    const int tile = blockIdx.x;
    if (tile >= g_num_tiles) return;
    const int e     = g_tile_e[tile];
    const int row0  = g_tile_row0[tile];
    const int nrows = g_tile_nrows[tile];
    const int n0    = blockIdx.y * BN;

    __shared__ __align__(16) char smA[2][BM*A_STRIDE];     // 2 x 10240
    __shared__ __align__(16) char smB[4][KC*B_STRIDE];     // 4 x 4608
    __shared__ int stok[BM];

    const int tid = threadIdx.x, lane = tid & 31, wid = tid >> 5;
    const int warpM = wid & 3, warpN = wid >> 2;

    if (tid < BM) stok[tid] = (tid < nrows) ? g_slot_token[row0 + tid] : 0;
    __syncthreads();

    const __nv_bfloat16* bsrc[4] = {
        g_wgh + (size_t)e*HID*FF, g_wgl + (size_t)e*HID*FF,
        g_wuh + (size_t)e*HID*FF, g_wul + (size_t)e*HID*FF };

    const uint32_t sa = smem_u32(smA);
    const uint32_t sbb = smem_u32(smB);

    float ag[2][4][4], au[2][4][4];
    #pragma unroll
    for (int i = 0; i < 2; i++)
        #pragma unroll
        for (int g = 0; g < 4; g++)
            #pragma unroll
            for (int r = 0; r < 4; r++) { ag[i][g][r] = 0.f; au[i][g][r] = 0.f; }

    for (int ch = 0; ch < HID/KC; ch++) {      // 32 chunks
        const int k0 = ch * KC;
        #pragma unroll
        for (int p = 0; p < 2; p++) {
            const __nv_bfloat16* xs = p ? g_xl : g_xh;
            #pragma unroll
            for (int t = 0; t < 2; t++) {
                int idx = tid + t*256;
                int row = idx >> 2, seg = idx & 3;
                cp16(sa + p*(BM*A_STRIDE) + row*A_STRIDE + seg*16,
                     xs + (size_t)stok[row]*HID + k0 + seg*8);
            }
        }
        {
            int row = tid >> 3, seg = tid & 7;
            #pragma unroll
            for (int p = 0; p < 4; p++)
                cp16(sbb + p*(KC*B_STRIDE) + row*B_STRIDE + seg*16,
                     bsrc[p] + (size_t)(k0+row)*FF + n0 + seg*8);
        }
        CP_COMMIT(); CP_WAIT0();
        __syncthreads();

        #pragma unroll
        for (int kk = 0; kk < 2; kk++) {
            uint32_t af[2][2][4];     // [plane][i]
            #pragma unroll
            for (int i = 0; i < 2; i++) {
                uint32_t ar = (uint32_t)(warpM*32 + i*16 + (lane & 15))*A_STRIDE
                              + kk*32 + (lane >> 4)*16;
                ldsm4(af[0][i], sa + ar);
                ldsm4(af[1][i], sa + BM*A_STRIDE + ar);
            }
            uint32_t br = (uint32_t)(kk*16 + (lane & 15))*B_STRIDE
                          + warpN*64 + (lane >> 4)*16;
            uint32_t bf[4][4][2];     // [plane][ngroup]
            #pragma unroll
            for (int p = 0; p < 4; p++) {
                uint32_t q0[4], q1[4];
                ldsm4t(q0, sbb + p*(KC*B_STRIDE) + br);
                ldsm4t(q1, sbb + p*(KC*B_STRIDE) + br + 32);
                bf[p][0][0]=q0[0]; bf[p][0][1]=q0[1];
                bf[p][1][0]=q0[2]; bf[p][1][1]=q0[3];
                bf[p][2][0]=q1[0]; bf[p][2][1]=q1[1];
                bf[p][3][0]=q1[2]; bf[p][3][1]=q1[3];
            }
            #pragma unroll
            for (int i = 0; i < 2; i++)
                #pragma unroll
                for (int g = 0; g < 4; g++) {
                    mma16816(ag[i][g], af[0][i], bf[0][g]);
                    mma16816(ag[i][g], af[0][i], bf[1][g]);
                    mma16816(ag[i][g], af[1][i], bf[0][g]);
                    mma16816(au[i][g], af[0][i], bf[2][g]);
                    mma16816(au[i][g], af[0][i], bf[3][g]);
                    mma16816(au[i][g], af[1][i], bf[2][g]);
                }
        }
        __syncthreads();
    }

    const int qr = lane >> 2;
    const int qc = 2 * (lane & 3);
    #pragma unroll
    for (int i = 0; i < 2; i++)
        #pragma unroll
        for (int g = 0; g < 4; g++) {
            int col = n0 + warpN*32 + g*8 + qc;
            #pragma unroll
            for (int half = 0; half < 2; half++) {
                int tm = warpM*32 + i*16 + qr + half*8;
                if (tm < nrows) {
                    float g0 = ag[i][g][half*2],   u0 = au[i][g][half*2];
                    float g1 = ag[i][g][half*2+1], u1 = au[i][g][half*2+1];
                    float v0 = (g0 / (1.f + __expf(-g0))) * u0;
                    float v1 = (g1 / (1.f + __expf(-g1))) * u1;
                    float hh0 = __bfloat162float(__float2bfloat16_rn(v0));
                    float hh1 = __bfloat162float(__float2bfloat16_rn(v1));
                    size_t off = (size_t)(row0 + tm) * FF + col;
                    *(uint32_t*)(g_hh + off) = pack_bf16(v0, v1);
                    *(uint32_t*)(g_hl + off) = pack_bf16(v0 - hh0, v1 - hh1);
                }
            }
        }
}

// ---------------- GEMM2: mma.sync bf16x3, down-proj -------------------------
__global__ void __launch_bounds__(256) gemm2_kernel()
{
    const int tile = blockIdx.x;
    if (tile >= g_num_tiles) return;
    const int e     = g_tile_e[tile];
    const int row0  = g_tile_row0[tile];
    const int nrows = g_tile_nrows[tile];
    const int n0    = blockIdx.y * BN;

    __shared__ __align__(16) char smA[2][BM*A_STRIDE];
    __shared__ __align__(16) char smB[2][KC*B_STRIDE];

    const int tid = threadIdx.x, lane = tid & 31, wid = tid >> 5;
    const int warpM = wid & 3, warpN = wid >> 2;

    const __nv_bfloat16* bsrc[2] = {
        g_wdh + (size_t)e*FF*HID, g_wdl + (size_t)e*FF*HID };

    const uint32_t sa = smem_u32(smA);
    const uint32_t sbb = smem_u32(smB);

    float acc[2][4][4];
    #pragma unroll
    for (int i = 0; i < 2; i++)
        #pragma unroll
        for (int g = 0; g < 4; g++)
            #pragma unroll
            for (int r = 0; r < 4; r++) acc[i][g][r] = 0.f;

    for (int ch = 0; ch < FF/KC; ch++) {       // 128 chunks
        const int k0 = ch * KC;
        #pragma unroll
        for (int p = 0; p < 2; p++) {
            const __nv_bfloat16* hs = p ? g_hl : g_hh;
            #pragma unroll
            for (int t = 0; t < 2; t++) {
                int idx = tid + t*256;
                int row = idx >> 2, seg = idx & 3;
                int r = row0 + row; if (r > NSLOT-1) r = NSLOT-1;
                cp16(sa + p*(BM*A_STRIDE) + row*A_STRIDE + seg*16,
                     hs + (size_t)r*FF + k0 + seg*8);
            }
        }
        {
            int row = tid >> 3, seg = tid & 7;
            #pragma unroll
            for (int p = 0; p < 2; p++)
                cp16(sbb + p*(KC*B_STRIDE) + row*B_STRIDE + seg*16,
                     bsrc[p] + (size_t)(k0+row)*HID + n0 + seg*8);
        }
        CP_COMMIT(); CP_WAIT0();
        __syncthreads();

        #pragma unroll
        for (int kk = 0; kk < 2; kk++) {
            uint32_t af[2][2][4];
            #pragma unroll
            for (int i = 0; i < 2; i++) {
                uint32_t ar = (uint32_t)(warpM*32 + i*16 + (lane & 15))*A_STRIDE
                              + kk*32 + (lane >> 4)*16;
                ldsm4(af[0][i], sa + ar);
                ldsm4(af[1][i], sa + BM*A_STRIDE + ar);
            }
            uint32_t br = (uint32_t)(kk*16 + (lane & 15))*B_STRIDE
                          + warpN*64 + (lane >> 4)*16;
            uint32_t bf[2][4][2];
            #pragma unroll
            for (int p = 0; p < 2; p++) {
                uint32_t q0[4], q1[4];
                ldsm4t(q0, sbb + p*(KC*B_STRIDE) + br);
                ldsm4t(q1, sbb + p*(KC*B_STRIDE) + br + 32);
                bf[p][0][0]=q0[0]; bf[p][0][1]=q0[1];
                bf[p][1][0]=q0[2]; bf[p][1][1]=q0[3];
                bf[p][2][0]=q1[0]; bf[p][2][1]=q1[1];
                bf[p][3][0]=q1[2]; bf[p][3][1]=q1[3];
            }
            #pragma unroll
            for (int i = 0; i < 2; i++)
                #pragma unroll
                for (int g = 0; g < 4; g++) {
                    mma16816(acc[i][g], af[0][i], bf[0][g]);
                    mma16816(acc[i][g], af[0][i], bf[1][g]);
                    mma16816(acc[i][g], af[1][i], bf[0][g]);
                }
        }
        __syncthreads();
    }

    const int qr = lane >> 2;
    const int qc = 2 * (lane & 3);
    #pragma unroll
    for (int i = 0; i < 2; i++)
        #pragma unroll
        for (int g = 0; g < 4; g++) {
            int col = n0 + warpN*32 + g*8 + qc;
            #pragma unroll
            for (int half = 0; half < 2; half++) {
                int tm = warpM*32 + i*16 + qr + half*8;
                if (tm < nrows) {
                    float2 v = make_float2(acc[i][g][half*2], acc[i][g][half*2+1]);
                    *(float2*)(g_dout + (size_t)(row0 + tm)*HID + col) = v;
                }
            }
        }
}

// ---------------- combine ----------------------------------------------------
__global__ void combine_kernel(float* __restrict__ out)
{
    const int t  = blockIdx.x;
    const int s0 = g_token_slot[t*2];
    const int s1 = g_token_slot[t*2+1];
    const float w0 = g_top_w[t*2];
    const float w1 = g_top_w[t*2+1];
    const int h = threadIdx.x << 2;
    float4 d0 = *(const float4*)(g_dout + (size_t)s0*HID + h);
    float4 d1 = *(const float4*)(g_dout + (size_t)s1*HID + h);
    float4 o;
    o.x = w0*d0.x + w1*d1.x;
    o.y = w0*d0.y + w1*d1.y;
    o.z = w0*d0.z + w1*d1.z;
    o.w = w0*d0.w + w1*d1.w;
    *(float4*)(out + (size_t)t*HID + h) = o;
}

// ---------------------------------------------------------------------------
extern "C" void kernel_launch(void* const* d_in, const int* in_sizes, int n_in,
                              void* d_out, int out_size)
{
    const float* x      = (const float*)d_in[0];
    const float* gate_w = (const float*)d_in[1];
    const float* w_gate = (const float*)d_in[2];
    const float* w_up   = (const float*)d_in[3];
    const float* w_down = (const float*)d_in[4];
    float* out = (float*)d_out;

    router_kernel<<<NT*32/256, 256>>>(x, gate_w);
    route_build_kernel<<<1, 256>>>();
    split_kernel<<<(NT*HID/4)/256, 256>>>(x, 0);
    split_kernel<<<(NE*HID*FF/4)/256, 256>>>(w_gate, 1);
    split_kernel<<<(NE*HID*FF/4)/256, 256>>>(w_up,   2);
    split_kernel<<<(NE*FF*HID/4)/256, 256>>>(w_down, 3);
    dim3 g1(MAX_TILES, FF/BN);    // 40 x 64
    gemm1_kernel<<<g1, 256>>>();
    dim3 g2(MAX_TILES, HID/BN);   // 40 x 16
    gemm2_kernel<<<g2, 256>>>();
    combine_kernel<<<NT, 256>>>(out);
}